// round 11
// baseline (speedup 1.0000x reference)
#include <cuda_runtime.h>
#include <cuda_bf16.h>

// diag-embed: out[i, j, k] = (j == k) ? x[i, j] : 0
// x: [8192, 176] fp32, out: [8192, 176, 176] fp32 (~1.015 GB of stores).
//
// R11: champion R4 body + sm_100a+ 256-bit stores (st.global.cs.v8.f32).
// One STG.256 per 32 B: halves store instructions and L1tex wavefronts per
// byte vs R4's STG.128, while keeping per-warp accesses fully contiguous
// (1024 B/warp/instr) — unlike R5's broken two-store stride-2 layout.
// One div/mod + one L2-hot LDG per 32 B group (44 chunks/row even -> a
// 2-chunk group never straddles a row). Grid shape frozen: 1184 x 256.

#define D_MODEL 176u
#define GPR 22u            // 8-float groups per output row (176/8)
#define BLOCKS 1184u       // 148 SMs * 8 blocks
#define THREADS 256u

__global__ __launch_bounds__(THREADS) void diag_embed_kernel(
        const float* __restrict__ x,
        float* __restrict__ out,
        unsigned ngroups) {
    const unsigned stride = BLOCKS * THREADS;
    unsigned p = blockIdx.x * THREADS + threadIdx.x;

    #pragma unroll 4
    for (; p < ngroups; p += stride) {
        unsigned rowg = p / GPR;                 // 32-bit magic div
        unsigned qp   = p - rowg * GPR;          // group index within row
        unsigned row  = rowg % D_MODEL;          // diag position in row

        float xv = __ldg(x + rowg);              // L1/L2-hot (x = 5.8 MB)

        unsigned c0 = qp * 8u;                   // first column of group
        float v0 = (c0      == row) ? xv : 0.f;
        float v1 = (c0 + 1u == row) ? xv : 0.f;
        float v2 = (c0 + 2u == row) ? xv : 0.f;
        float v3 = (c0 + 3u == row) ? xv : 0.f;
        float v4 = (c0 + 4u == row) ? xv : 0.f;
        float v5 = (c0 + 5u == row) ? xv : 0.f;
        float v6 = (c0 + 6u == row) ? xv : 0.f;
        float v7 = (c0 + 7u == row) ? xv : 0.f;

        // Single 256-bit streaming store: warp writes 1024 contiguous bytes.
        float* dst = out + (size_t)p * 8u;
        asm volatile(
            "st.global.cs.v8.f32 [%0], {%1, %2, %3, %4, %5, %6, %7, %8};"
            :: "l"(dst),
               "f"(v0), "f"(v1), "f"(v2), "f"(v3),
               "f"(v4), "f"(v5), "f"(v6), "f"(v7)
            : "memory");
    }
}

extern "C" void kernel_launch(void* const* d_in, const int* in_sizes, int n_in,
                              void* d_out, int out_size) {
    const float* x = (const float*)d_in[0];
    float* out = (float*)d_out;

    unsigned ngroups = (unsigned)(out_size / 8); // 31,719,424 8-float groups

    diag_embed_kernel<<<BLOCKS, THREADS>>>(x, out, ngroups);
}

// round 12
// speedup vs baseline: 1.0565x; 1.0565x over previous
#include <cuda_runtime.h>
#include <cuda_bf16.h>

// diag-embed: out[i, j, k] = (j == k) ? x[i, j] : 0
// x: [8192, 176] fp32, out: [8192, 176, 176] fp32 (~1.015 GB of stores).
//
// R12: final shape micro-test on the R4 champion body. Identical per-thread
// work; concurrency repacked as 592 blocks x 512 threads (4 blocks/SM, same
// 2048 threads/SM as the champion's 8x256). Everything proven load-bearing
// is frozen:
//   - fine-grained whole-grid interleaved store stream
//   - branchless diagonal insertion (unconditional L2-hot LDG + 4 selects)
//   - 32-bit magic div/mod
//   - __stcs STG.128 (beat STG.256, stwt, two-pass, slabs, warp-tiles)
//   - unroll 8

#define D_MODEL 176u
#define CPR 44u            // float4 chunks per output row
#define BLOCKS 592u        // 148 SMs * 4 blocks
#define THREADS 512u       // same 2048 threads/SM as champion

__global__ __launch_bounds__(THREADS) void diag_embed_kernel(
        const float* __restrict__ x,
        float4* __restrict__ out,
        unsigned n4) {
    const unsigned stride = BLOCKS * THREADS;
    unsigned g = blockIdx.x * THREADS + threadIdx.x;

    #pragma unroll 8
    for (; g < n4; g += stride) {
        unsigned rowg = g / CPR;                 // 32-bit magic div
        unsigned q    = g - rowg * CPR;          // chunk within row
        unsigned row  = rowg % D_MODEL;          // diag position in row

        float xv = __ldg(x + rowg);              // L1/L2-hot (x = 5.8 MB)

        unsigned c0 = q * 4u;
        float4 v;
        v.x = (c0        == row) ? xv : 0.f;
        v.y = (c0 + 1u   == row) ? xv : 0.f;
        v.z = (c0 + 2u   == row) ? xv : 0.f;
        v.w = (c0 + 3u   == row) ? xv : 0.f;

        __stcs(out + g, v);                      // streaming store
    }
}

extern "C" void kernel_launch(void* const* d_in, const int* in_sizes, int n_in,
                              void* d_out, int out_size) {
    const float* x = (const float*)d_in[0];
    float4* out = (float4*)d_out;

    unsigned n4 = (unsigned)(out_size / 4);      // 63,438,848 float4 chunks

    diag_embed_kernel<<<BLOCKS, THREADS>>>(x, out, n4);
}